// round 16
// baseline (speedup 1.0000x reference)
#include <cuda_runtime.h>
#include <cuda_bf16.h>
#include <math.h>
#include <stdint.h>

#define HC   128
#define NH   8
#define COLS 256
#define MAXN 50000
#define MAXM 400000
#define TM   128   // rows per tile (proj/out)
#define TE   128   // edges per tile (edge kernel)

typedef unsigned long long ull;

// Scratch (device globals — no allocation allowed)
__device__ float g_q[MAXN * HC];
__device__ float g_k[MAXN * HC];
__device__ float g_v[MAXN * HC];
__device__ float g_agg[MAXN * HC];
__device__ float g_denom[MAXN * NH];
__device__ float g_ex[MAXM * NH];

__device__ __forceinline__ uint32_t smem_u32(const void* p) {
    uint32_t a;
    asm("{ .reg .u64 t; cvta.to.shared.u64 t, %1; cvt.u32.u64 %0, t; }"
        : "=r"(a) : "l"(p));
    return a;
}

// ---------------------------------------------------------------------------
// mma.sync / ldmatrix (base PTX ISA — valid for compute_103)
// ---------------------------------------------------------------------------
#define MMA_BF16(c, a, b) \
    asm volatile( \
        "mma.sync.aligned.m16n8k16.row.col.f32.bf16.bf16.f32 " \
        "{%0,%1,%2,%3}, {%4,%5,%6,%7}, {%8,%9}, {%0,%1,%2,%3};" \
        : "+f"((c)[0]), "+f"((c)[1]), "+f"((c)[2]), "+f"((c)[3]) \
        : "r"((a)[0]), "r"((a)[1]), "r"((a)[2]), "r"((a)[3]), \
          "r"((b)[0]), "r"((b)[1]))

#define LDSM_X4(r, addr) \
    asm volatile("ldmatrix.sync.aligned.m8n8.x4.shared.b16 {%0,%1,%2,%3}, [%4];" \
        : "=r"((r)[0]), "=r"((r)[1]), "=r"((r)[2]), "=r"((r)[3]) : "r"(addr))

// Row pitch 136 bf16 = 272 B (17x16B, conflict-free ldmatrix).
#define PITCHB  272
#define SPLIT_S 34816   // [128 rows][PITCHB] split plane

__device__ __forceinline__ void split_store(char* hi_p, char* lo_p, float2 x) {
    __nv_bfloat162 hi2 = __floats2bfloat162_rn(x.x, x.y);
    float r0 = x.x - __bfloat162float(hi2.x);
    float r1 = x.y - __bfloat162float(hi2.y);
    __nv_bfloat162 lo2 = __floats2bfloat162_rn(r0, r1);
    *(uint32_t*)hi_p = *(uint32_t*)&hi2;
    *(uint32_t*)lo_p = *(uint32_t*)&lo2;
}

// ---------------- SMEM layouts ----------------
// edge kernel (R9 staging, overlapped epilogue/staging; dbl-buffered idx)
#define SM_WB   0
#define SM_WB_S 69632
#define SM_WB_P 34816
#define SM_A    139264
#define SM_A_S  34816
#define SM_PART 208896      // [4 wn][128][8] f32 = 16384
#define SM_QI   225280      // [2][128] int = 1024
#define SM_KI   226304      // [2][128] int = 1024
#define SM_EDGE_TOTAL 227328
// proj/out kernels
#define OM_W0   0
#define OM_W1   69632
#define OM_A    139264
#define OM_TOTAL 208896

// ---------------------------------------------------------------------------
// 128x128x128 split-3 MMA core (proj/out)
// ---------------------------------------------------------------------------
__device__ __forceinline__ void mma_tile_128(
    float acc[2][4][4], uint32_t a_base, uint32_t b_base)
{
#pragma unroll
    for (int mt = 0; mt < 2; mt++)
#pragma unroll
        for (int nt = 0; nt < 4; nt++)
#pragma unroll
            for (int el = 0; el < 4; el++) acc[mt][nt][el] = 0.f;

#pragma unroll 2
    for (int ks = 0; ks < 8; ks++) {
        uint32_t bh[4][2], bl[4][2], ah[2][4], al[2][4];
        uint32_t bk = b_base + (uint32_t)ks * 32;
#pragma unroll
        for (int u2 = 0; u2 < 2; u2++) {
            uint32_t tmp[4];
            LDSM_X4(tmp, bk + (uint32_t)(u2 * 16) * PITCHB);
            bh[2*u2][0] = tmp[0]; bh[2*u2][1] = tmp[1];
            bh[2*u2+1][0] = tmp[2]; bh[2*u2+1][1] = tmp[3];
            LDSM_X4(tmp, bk + SPLIT_S + (uint32_t)(u2 * 16) * PITCHB);
            bl[2*u2][0] = tmp[0]; bl[2*u2][1] = tmp[1];
            bl[2*u2+1][0] = tmp[2]; bl[2*u2+1][1] = tmp[3];
        }
        uint32_t ak_ = a_base + (uint32_t)ks * 32;
#pragma unroll
        for (int mt = 0; mt < 2; mt++) {
            LDSM_X4(ah[mt], ak_ + (uint32_t)(mt * 16) * PITCHB);
            LDSM_X4(al[mt], ak_ + SPLIT_S + (uint32_t)(mt * 16) * PITCHB);
        }
#pragma unroll
        for (int mt = 0; mt < 2; mt++)
#pragma unroll
            for (int nt = 0; nt < 4; nt++) {
                MMA_BF16(acc[mt][nt], ah[mt], bh[nt]);
                MMA_BF16(acc[mt][nt], ah[mt], bl[nt]);
                MMA_BF16(acc[mt][nt], al[mt], bh[nt]);
            }
    }
}

__device__ __forceinline__ void store_acc_128(
    float acc[2][4][4], float* outp, int nb,
    int wm, int wn, int g, int t4, int n)
{
#pragma unroll
    for (int mt = 0; mt < 2; mt++)
#pragma unroll
        for (int rh = 0; rh < 2; rh++) {
            int row = nb + wm * 32 + mt * 16 + g + rh * 8;
            if (row < n) {
#pragma unroll
                for (int nt = 0; nt < 4; nt++) {
                    int col = wn * 32 + nt * 8 + t4 * 2;
                    *(float2*)&outp[(size_t)row * HC + col] =
                        make_float2(acc[mt][nt][rh*2], acc[mt][nt][rh*2+1]);
                }
            }
        }
}

// ---------------------------------------------------------------------------
// Init kernels (agg split in halves so k_proj lands in profiled 4th slot)
// ---------------------------------------------------------------------------
__global__ void k_init_agg(int lo, int hi) {
    int i = lo + blockIdx.x * blockDim.x + threadIdx.x;
    if (i < hi) g_agg[i] = 0.0f;
}
__global__ void k_init_denom(int n) {
    int i = blockIdx.x * blockDim.x + threadIdx.x;
    if (i < n * NH) g_denom[i] = 0.0f;
}

// ---------------------------------------------------------------------------
// Projections, weights-resident (validated) — in profiled slot this round
// ---------------------------------------------------------------------------
__global__ __launch_bounds__(512, 1) void k_proj_mma(
    const float* __restrict__ query, const float* __restrict__ key,
    const float* __restrict__ Wq, const float* __restrict__ Wkv, int n)
{
    extern __shared__ char smem[];
    uint32_t sbase = smem_u32(smem);

    int tid  = threadIdx.x;
    int warp = tid >> 5;
    int lane = tid & 31;
    int wm   = warp >> 2;
    int wn   = warp & 3;
    int g    = lane >> 2;
    int t4   = lane & 3;

    uint32_t aoff = (uint32_t)(((lane & 7) + 8 * ((lane >> 3) & 1)) * PITCHB
                               + ((lane >> 4) & 1) * 16);
    uint32_t boff = (uint32_t)(((lane & 7) + 8 * ((lane >> 4) & 1)) * PITCHB
                               + ((lane >> 3) & 1) * 16);
    uint32_t a_base = sbase + OM_A  + (uint32_t)(wm * 32) * PITCHB + aoff;
    uint32_t b0     = sbase + OM_W0 + (uint32_t)(wn * 32) * PITCHB + boff;
    uint32_t b1     = sbase + OM_W1 + (uint32_t)(wn * 32) * PITCHB + boff;

    int ntiles = (n + TM - 1) / TM;
    float acc[2][4][4];

    // pass 1: Wq resident
    for (int i = tid; i < 128 * 64; i += 512) {
        int nc = i >> 6, kp = i & 63;
        float2 w = make_float2(Wq[(2 * kp)     * HC + nc],
                               Wq[(2 * kp + 1) * HC + nc]);
        size_t off = (size_t)nc * PITCHB + (size_t)kp * 4;
        split_store(smem + OM_W0 + off, smem + OM_W0 + SPLIT_S + off, w);
    }
    for (int tile = blockIdx.x; tile < ntiles; tile += gridDim.x) {
        int nb = tile * TM;
        __syncthreads();
        for (int i = tid; i < TM * 64; i += 512) {
            int r = i >> 6, cp = i & 63;
            int row = nb + r;
            float2 x = (row < n) ? ((const float2*)query)[(size_t)row * 64 + cp]
                                 : make_float2(0.f, 0.f);
            size_t off = (size_t)r * PITCHB + (size_t)cp * 4;
            split_store(smem + OM_A + off, smem + OM_A + SPLIT_S + off, x);
        }
        __syncthreads();
        mma_tile_128(acc, a_base, b0);
        store_acc_128(acc, g_q, nb, wm, wn, g, t4, n);
    }

    // pass 2: Wk + Wv resident, key staged once
    __syncthreads();
    for (int i = tid; i < 128 * 64; i += 512) {
        int nc = i >> 6, kp = i & 63;
        float2 wk = make_float2(Wkv[(2 * kp)     * COLS + nc],
                                Wkv[(2 * kp + 1) * COLS + nc]);
        float2 wv = make_float2(Wkv[(2 * kp)     * COLS + HC + nc],
                                Wkv[(2 * kp + 1) * COLS + HC + nc]);
        size_t off = (size_t)nc * PITCHB + (size_t)kp * 4;
        split_store(smem + OM_W0 + off, smem + OM_W0 + SPLIT_S + off, wk);
        split_store(smem + OM_W1 + off, smem + OM_W1 + SPLIT_S + off, wv);
    }
    for (int tile = blockIdx.x; tile < ntiles; tile += gridDim.x) {
        int nb = tile * TM;
        __syncthreads();
        for (int i = tid; i < TM * 64; i += 512) {
            int r = i >> 6, cp = i & 63;
            int row = nb + r;
            float2 x = (row < n) ? ((const float2*)key)[(size_t)row * 64 + cp]
                                 : make_float2(0.f, 0.f);
            size_t off = (size_t)r * PITCHB + (size_t)cp * 4;
            split_store(smem + OM_A + off, smem + OM_A + SPLIT_S + off, x);
        }
        __syncthreads();
        mma_tile_128(acc, a_base, b0);
        store_acc_128(acc, g_k, nb, wm, wn, g, t4, n);
        mma_tile_128(acc, a_base, b1);
        store_acc_128(acc, g_v, nb, wm, wn, g, t4, n);
    }
}

// ---------------------------------------------------------------------------
// Edge kernel: R9 GEMM core; staging of tile t+1 is moved into the epilogue
// phase (overlaps combine/exp/denom). 2 syncs/tile instead of 3.
// Epilogue fuses exp + denom (no segment-max — R14/R15 validated).
// ---------------------------------------------------------------------------
__global__ __launch_bounds__(512, 1) void k_edge_mma(
    const float* __restrict__ paired, const float* __restrict__ Wb,
    const int* __restrict__ qidx, const int* __restrict__ kidx,
    float* __restrict__ out_logit, int m)
{
    extern __shared__ char smem[];
    uint32_t sbase = smem_u32(smem);

    int tid  = threadIdx.x;
    int warp = tid >> 5;
    int lane = tid & 31;
    int wm   = warp >> 2;
    int wn   = warp & 3;
    int g    = lane >> 2;
    int t4   = lane & 3;

    int*   s_qi   = (int*)(smem + SM_QI);   // [2][128]
    int*   s_ki   = (int*)(smem + SM_KI);   // [2][128]
    float* s_part = (float*)(smem + SM_PART);

    // Stage Wb^T hi/lo, interleaved mul/add columns, once per CTA
    for (int i = tid; i < 2 * 128 * 64; i += 512) {
        int kp = i & 63;
        int nc = (i >> 6) & 127;
        int p  = i >> 13;
        int wn_ = nc >> 5, ln = nc & 31;
        int u = ln >> 4, bias = (ln >> 3) & 1, off = ln & 7;
        int ch   = p * 64 + wn_ * 16 + u * 8 + off;
        int wcol = bias * 128 + ch;
        float2 w = make_float2(Wb[(2 * kp)     * COLS + wcol],
                               Wb[(2 * kp + 1) * COLS + wcol]);
        size_t off_b = (size_t)p * SM_WB_P + (size_t)nc * PITCHB + (size_t)kp * 4;
        split_store(smem + SM_WB + off_b, smem + SM_WB + SM_WB_S + off_b, w);
    }

    uint32_t aoff = (uint32_t)(((lane & 7) + 8 * ((lane >> 3) & 1)) * PITCHB
                               + ((lane >> 4) & 1) * 16);
    uint32_t boff = (uint32_t)(((lane & 7) + 8 * ((lane >> 4) & 1)) * PITCHB
                               + ((lane >> 3) & 1) * 16);
    uint32_t a_base = sbase + SM_A  + (uint32_t)(wm * 32) * PITCHB + aoff;
    uint32_t b_base = sbase + SM_WB + (uint32_t)(wn * 32) * PITCHB + boff;

    int ntiles = (m + TE - 1) / TE;
    int stride = gridDim.x;
    int t0 = blockIdx.x;

    auto stage_A = [&](int t) {
        int ebase = t * TE;
        for (int i = tid; i < TE * 64; i += 512) {
            int r = i >> 6, cp = i & 63;
            int e = ebase + r;
            float2 x = (e < m) ? ((const float2*)paired)[(size_t)e * 64 + cp]
                               : make_float2(0.f, 0.f);
            size_t off_a = (size_t)r * PITCHB + (size_t)cp * 4;
            split_store(smem + SM_A + off_a, smem + SM_A + SM_A_S + off_a, x);
        }
    };
    auto stage_idx = [&](int t, int b) {
        if (tid < TE) {
            int e = t * TE + tid;
            s_qi[b * 128 + tid] = (e < m) ? qidx[e] : 0;
            s_ki[b * 128 + tid] = (e < m) ? kidx[e] : 0;
        }
    };

    // prologue: stage first tile
    if (t0 < ntiles) { stage_A(t0); stage_idx(t0, 0); }
    __syncthreads();

    int buf = 0;
    for (int tile = t0; tile < ntiles; tile += stride) {
        int ebase = tile * TE;
        const int* qi_b = s_qi + buf * 128;
        const int* ki_b = s_ki + buf * 128;

        float part[4][2];
#pragma unroll
        for (int a = 0; a < 4; a++) { part[a][0] = 0.f; part[a][1] = 0.f; }

#pragma unroll
        for (int p = 0; p < 2; p++) {
            float acc[2][4][4];
#pragma unroll
            for (int mt = 0; mt < 2; mt++)
#pragma unroll
                for (int nt = 0; nt < 4; nt++)
#pragma unroll
                    for (int el = 0; el < 4; el++) acc[mt][nt][el] = 0.f;

#pragma unroll 2
            for (int ks = 0; ks < 8; ks++) {
                uint32_t bh[4][2], bl[4][2], ah[2][4], al[2][4];
                uint32_t bk = b_base + (uint32_t)p * SM_WB_P + (uint32_t)ks * 32;
#pragma unroll
                for (int u2 = 0; u2 < 2; u2++) {
                    uint32_t tmp[4];
                    LDSM_X4(tmp, bk + (uint32_t)(u2 * 16) * PITCHB);
                    bh[2*u2][0] = tmp[0]; bh[2*u2][1] = tmp[1];
                    bh[2*u2+1][0] = tmp[2]; bh[2*u2+1][1] = tmp[3];
                    LDSM_X4(tmp, bk + SM_WB_S + (uint32_t)(u2 * 16) * PITCHB);
                    bl[2*u2][0] = tmp[0]; bl[2*u2][1] = tmp[1];
                    bl[2*u2+1][0] = tmp[2]; bl[2*u2+1][1] = tmp[3];
                }
                uint32_t ak_ = a_base + (uint32_t)ks * 32;
#pragma unroll
                for (int mt = 0; mt < 2; mt++) {
                    LDSM_X4(ah[mt], ak_ + (uint32_t)(mt * 16) * PITCHB);
                    LDSM_X4(al[mt], ak_ + SM_A_S + (uint32_t)(mt * 16) * PITCHB);
                }
#pragma unroll
                for (int mt = 0; mt < 2; mt++)
#pragma unroll
                    for (int nt = 0; nt < 4; nt++) {
                        MMA_BF16(acc[mt][nt], ah[mt], bh[nt]);
                        MMA_BF16(acc[mt][nt], ah[mt], bl[nt]);
                        MMA_BF16(acc[mt][nt], al[mt], bh[nt]);
                    }
            }

            // per-pass epilogue: bias-modulated q/k reduction
#pragma unroll
            for (int mt = 0; mt < 2; mt++)
#pragma unroll
                for (int rh = 0; rh < 2; rh++) {
                    int eli = wm * 32 + mt * 16 + g + rh * 8;
                    const float* qrow = g_q + (size_t)qi_b[eli] * HC;
                    const float* krow = g_k + (size_t)ki_b[eli] * HC;
#pragma unroll
                    for (int u = 0; u < 2; u++) {
                        int c = p * 64 + wn * 16 + u * 8 + t4 * 2;
                        float2 q2 = *(const float2*)(qrow + c);
                        float2 k2 = *(const float2*)(krow + c);
                        float bm0 = acc[mt][2*u][rh*2],   bm1 = acc[mt][2*u][rh*2+1];
                        float ba0 = acc[mt][2*u+1][rh*2], ba1 = acc[mt][2*u+1][rh*2+1];
                        float qk0 = q2.x * k2.x;
                        float qk1 = q2.y * k2.y;
                        part[mt*2+rh][0] += fmaf(qk0, bm0, qk0) + q2.x * ba0;
                        part[mt*2+rh][1] += fmaf(qk1, bm1, qk1) + q2.y * ba1;
                    }
                }
        }

        // store partials
#pragma unroll
        for (int mt = 0; mt < 2; mt++)
#pragma unroll
            for (int rh = 0; rh < 2; rh++) {
                int eli = wm * 32 + mt * 16 + g + rh * 8;
                float2* sp = (float2*)&s_part[wn * 1024 + eli * 8 + t4 * 2];
                *sp = make_float2(part[mt*2+rh][0], part[mt*2+rh][1]);
            }
        __syncthreads();   // all LDSM of SM_A done; s_part visible

        // --- stage NEXT tile into SM_A + idx[buf^1] (overlaps combine) ---
        int tn = tile + stride;
        if (tn < ntiles) { stage_A(tn); stage_idx(tn, buf ^ 1); }

        // --- combine, emit logit, exp, denom accumulation ---
#pragma unroll
        for (int j = 0; j < 2; j++) {
            int i  = tid + j * 512;
            int el = i >> 3, h = i & 7;
            int e  = ebase + el;
            if (e < m) {
                float lg = (s_part[i] + s_part[1024 + i])
                         + (s_part[2048 + i] + s_part[3072 + i]);
                out_logit[e * NH + h] = lg;
                float ex = expf(lg);
                g_ex[e * NH + h] = ex;
                atomicAdd(&g_denom[qi_b[el] * NH + h], ex);
            }
        }
        __syncthreads();   // staged A + idx visible; s_part free
        buf ^= 1;
    }
}

// ---------------------------------------------------------------------------
// scatter (normalized): agg[qi] += (ex/denom) * v[ki]   (R9-validated)
// ---------------------------------------------------------------------------
__global__ void k_scatter(const int* __restrict__ qidx,
                          const int* __restrict__ kidx, int m)
{
    int i = blockIdx.x * blockDim.x + threadIdx.x;
    if (i >= m * 32) return;
    int e  = i >> 5;
    int c4 = (i & 31) << 2;
    int qi = qidx[e];
    float4 v  = *(const float4*)&g_v[kidx[e] * HC + c4];
    float4 ex = *(const float4*)&g_ex[(e << 3) + (c4 & 7)];
    float4 dn = *(const float4*)&g_denom[qi * NH + (c4 & 7)];
    float4 val = make_float4((ex.x / dn.x) * v.x, (ex.y / dn.y) * v.y,
                             (ex.z / dn.z) * v.z, (ex.w / dn.w) * v.w);
    atomicAdd((float4*)&g_agg[qi * HC + c4], val);
}

// ---------------------------------------------------------------------------
// result = agg @ Wo, weights-resident (validated)
// ---------------------------------------------------------------------------
__global__ __launch_bounds__(512, 1) void k_out_mma(
    const float* __restrict__ Wo, float* __restrict__ out, int n)
{
    extern __shared__ char smem[];
    uint32_t sbase = smem_u32(smem);

    int tid  = threadIdx.x;
    int warp = tid >> 5;
    int lane = tid & 31;
    int wm   = warp >> 2;
    int wn   = warp & 3;
    int g    = lane >> 2;
    int t4   = lane & 3;

    uint32_t aoff = (uint32_t)(((lane & 7) + 8 * ((lane >> 3) & 1)) * PITCHB
                               + ((lane >> 4) & 1) * 16);
    uint32_t boff = (uint32_t)(((lane & 7) + 8 * ((lane >> 4) & 1)) * PITCHB
                               + ((lane >> 3) & 1) * 16);
    uint32_t a_base = sbase + OM_A  + (uint32_t)(wm * 32) * PITCHB + aoff;
    uint32_t b0     = sbase + OM_W0 + (uint32_t)(wn * 32) * PITCHB + boff;

    for (int i = tid; i < 128 * 64; i += 512) {
        int nc = i >> 6, kp = i & 63;
        float2 w = make_float2(Wo[(2 * kp)     * HC + nc],
                               Wo[(2 * kp + 1) * HC + nc]);
        size_t off = (size_t)nc * PITCHB + (size_t)kp * 4;
        split_store(smem + OM_W0 + off, smem + OM_W0 + SPLIT_S + off, w);
    }

    int ntiles = (n + TM - 1) / TM;
    float acc[2][4][4];
    for (int tile = blockIdx.x; tile < ntiles; tile += gridDim.x) {
        int nb = tile * TM;
        __syncthreads();
        for (int i = tid; i < TM * 64; i += 512) {
            int r = i >> 6, cp = i & 63;
            int row = nb + r;
            float2 x = (row < n) ? ((const float2*)g_agg)[(size_t)row * 64 + cp]
                                 : make_float2(0.f, 0.f);
            size_t off = (size_t)r * PITCHB + (size_t)cp * 4;
            split_store(smem + OM_A + off, smem + OM_A + SPLIT_S + off, x);
        }
        __syncthreads();
        mma_tile_128(acc, a_base, b0);
        store_acc_128(acc, out, nb, wm, wn, g, t4, n);
    }
}

// ---------------------------------------------------------------------------
extern "C" void kernel_launch(void* const* d_in, const int* in_sizes, int n_in,
                              void* d_out, int out_size)
{
    const float* query  = (const float*)d_in[0];
    const float* key    = (const float*)d_in[1];
    const int*   qidx   = (const int*)  d_in[2];
    const int*   kidx   = (const int*)  d_in[3];
    const float* paired = (const float*)d_in[4];
    const float* Wq     = (const float*)d_in[5];
    const float* Wkv    = (const float*)d_in[6];
    const float* Wb     = (const float*)d_in[7];
    const float* Wo     = (const float*)d_in[8];

    int n = in_sizes[0] / HC;   // 50000
    int m = in_sizes[2];        // 400000

    float* out_result = (float*)d_out;           // n*HC
    float* out_logit  = (float*)d_out + n * HC;  // m*NH

    cudaFuncSetAttribute(k_edge_mma, cudaFuncAttributeMaxDynamicSharedMemorySize,
                         SM_EDGE_TOTAL);
    cudaFuncSetAttribute(k_proj_mma, cudaFuncAttributeMaxDynamicSharedMemorySize,
                         OM_TOTAL);
    cudaFuncSetAttribute(k_out_mma, cudaFuncAttributeMaxDynamicSharedMemorySize,
                         OM_TOTAL);

    int dev = 0, nsm = 148;
    cudaGetDevice(&dev);
    cudaDeviceGetAttribute(&nsm, cudaDevAttrMultiProcessorCount, dev);

    int etiles = (m + TE - 1) / TE;
    int egrid  = etiles < nsm ? etiles : nsm;
    int ptiles = (n + TM - 1) / TM;
    int pgrid  = ptiles < nsm ? ptiles : nsm;

    int half = (n * HC) / 2;

    // k_proj_mma takes the profiled (4th) slot this round.
    k_init_agg<<<(half + 255) / 256, 256>>>(0, half);                    // 1
    k_init_agg<<<(n * HC - half + 255) / 256, 256>>>(half, n * HC);      // 2
    k_init_denom<<<(n * NH + 255) / 256, 256>>>(n);                      // 3
    k_proj_mma<<<pgrid, 512, OM_TOTAL>>>(query, key, Wq, Wkv, n);        // 4
    k_edge_mma<<<egrid, 512, SM_EDGE_TOTAL>>>(paired, Wb, qidx, kidx,    // 5
                                              out_logit, m);
    k_scatter<<<(m * 32 + 255) / 256, 256>>>(qidx, kidx, m);             // 6
    k_out_mma<<<pgrid, 512, OM_TOTAL>>>(Wo, out_result, n);              // 7
}

// round 17
// speedup vs baseline: 1.0050x; 1.0050x over previous
#include <cuda_runtime.h>
#include <cuda_bf16.h>
#include <math.h>
#include <stdint.h>

#define HC   128
#define NH   8
#define COLS 256
#define MAXN 50000
#define MAXM 400000
#define TE   128   // edges per tile (edge kernel)
#define TP   64    // rows per tile (proj/out, 2 CTAs/SM)

typedef unsigned long long ull;

// Scratch (device globals — no allocation allowed)
__device__ float g_q[MAXN * HC];
__device__ float g_k[MAXN * HC];
__device__ float g_v[MAXN * HC];
__device__ float g_agg[MAXN * HC];
__device__ float g_denom[MAXN * NH];
__device__ float g_ex[MAXM * NH];

__device__ __forceinline__ uint32_t smem_u32(const void* p) {
    uint32_t a;
    asm("{ .reg .u64 t; cvta.to.shared.u64 t, %1; cvt.u32.u64 %0, t; }"
        : "=r"(a) : "l"(p));
    return a;
}

// ---------------------------------------------------------------------------
// mma.sync / ldmatrix (base PTX ISA — valid for compute_103)
// ---------------------------------------------------------------------------
#define MMA_BF16(c, a, b) \
    asm volatile( \
        "mma.sync.aligned.m16n8k16.row.col.f32.bf16.bf16.f32 " \
        "{%0,%1,%2,%3}, {%4,%5,%6,%7}, {%8,%9}, {%0,%1,%2,%3};" \
        : "+f"((c)[0]), "+f"((c)[1]), "+f"((c)[2]), "+f"((c)[3]) \
        : "r"((a)[0]), "r"((a)[1]), "r"((a)[2]), "r"((a)[3]), \
          "r"((b)[0]), "r"((b)[1]))

#define LDSM_X4(r, addr) \
    asm volatile("ldmatrix.sync.aligned.m8n8.x4.shared.b16 {%0,%1,%2,%3}, [%4];" \
        : "=r"((r)[0]), "=r"((r)[1]), "=r"((r)[2]), "=r"((r)[3]) : "r"(addr))

// Row pitch 136 bf16 = 272 B (17x16B, conflict-free ldmatrix).
#define PITCHB  272
#define SPLIT_S 34816   // split-plane stride for 128-row buffers

__device__ __forceinline__ void split_store(char* hi_p, char* lo_p, float2 x) {
    __nv_bfloat162 hi2 = __floats2bfloat162_rn(x.x, x.y);
    float r0 = x.x - __bfloat162float(hi2.x);
    float r1 = x.y - __bfloat162float(hi2.y);
    __nv_bfloat162 lo2 = __floats2bfloat162_rn(r0, r1);
    *(uint32_t*)hi_p = *(uint32_t*)&hi2;
    *(uint32_t*)lo_p = *(uint32_t*)&lo2;
}

// ---------------- SMEM layouts ----------------
// edge kernel (R15-exact, frozen)
#define SM_WB   0
#define SM_WB_S 69632
#define SM_WB_P 34816
#define SM_A    139264
#define SM_A_S  34816
#define SM_PART 208896
#define SM_QI   225280
#define SM_KI   225792
#define SM_EDGE_TOTAL 226304
// proj/out kernels: W [2 split][128][PITCHB] + A [2 split][64][PITCHB]
#define PM_W    0
#define PM_A    69632
#define PM_AS   17408      // A split stride (64 rows)
#define PM_TOTAL 104448    // 2 CTAs/SM

// ---------------------------------------------------------------------------
// Warp-local 32x128 (rows x cols) split-3 MMA: acc += A * B^T.
// a_sp / b_sp are the split-plane strides of the A / B buffers.
// ---------------------------------------------------------------------------
__device__ __forceinline__ void mma_warp_tile(
    float acc[2][4][4], uint32_t a_base, uint32_t b_base,
    uint32_t a_sp, uint32_t b_sp)
{
#pragma unroll
    for (int mt = 0; mt < 2; mt++)
#pragma unroll
        for (int nt = 0; nt < 4; nt++)
#pragma unroll
            for (int el = 0; el < 4; el++) acc[mt][nt][el] = 0.f;

#pragma unroll 2
    for (int ks = 0; ks < 8; ks++) {
        uint32_t bh[4][2], bl[4][2], ah[2][4], al[2][4];
        uint32_t bk = b_base + (uint32_t)ks * 32;
#pragma unroll
        for (int u2 = 0; u2 < 2; u2++) {
            uint32_t tmp[4];
            LDSM_X4(tmp, bk + (uint32_t)(u2 * 16) * PITCHB);
            bh[2*u2][0] = tmp[0]; bh[2*u2][1] = tmp[1];
            bh[2*u2+1][0] = tmp[2]; bh[2*u2+1][1] = tmp[3];
            LDSM_X4(tmp, bk + b_sp + (uint32_t)(u2 * 16) * PITCHB);
            bl[2*u2][0] = tmp[0]; bl[2*u2][1] = tmp[1];
            bl[2*u2+1][0] = tmp[2]; bl[2*u2+1][1] = tmp[3];
        }
        uint32_t ak_ = a_base + (uint32_t)ks * 32;
#pragma unroll
        for (int mt = 0; mt < 2; mt++) {
            LDSM_X4(ah[mt], ak_ + (uint32_t)(mt * 16) * PITCHB);
            LDSM_X4(al[mt], ak_ + a_sp + (uint32_t)(mt * 16) * PITCHB);
        }
#pragma unroll
        for (int mt = 0; mt < 2; mt++)
#pragma unroll
            for (int nt = 0; nt < 4; nt++) {
                MMA_BF16(acc[mt][nt], ah[mt], bh[nt]);
                MMA_BF16(acc[mt][nt], ah[mt], bl[nt]);
                MMA_BF16(acc[mt][nt], al[mt], bh[nt]);
            }
    }
}

__device__ __forceinline__ void store_acc_warp(
    float acc[2][4][4], float* outp, int nb,
    int wm, int wn, int g, int t4, int n)
{
#pragma unroll
    for (int mt = 0; mt < 2; mt++)
#pragma unroll
        for (int rh = 0; rh < 2; rh++) {
            int row = nb + wm * 32 + mt * 16 + g + rh * 8;
            if (row < n) {
#pragma unroll
                for (int nt = 0; nt < 4; nt++) {
                    int col = wn * 32 + nt * 8 + t4 * 2;
                    *(float2*)&outp[(size_t)row * HC + col] =
                        make_float2(acc[mt][nt][rh*2], acc[mt][nt][rh*2+1]);
                }
            }
        }
}

// ---------------------------------------------------------------------------
// Init kernels
// ---------------------------------------------------------------------------
__global__ void k_init_agg(int lo, int hi) {
    int i = lo + blockIdx.x * blockDim.x + threadIdx.x;
    if (i < hi) g_agg[i] = 0.0f;
}
__global__ void k_init_denom(int n) {
    int i = blockIdx.x * blockDim.x + threadIdx.x;
    if (i < n * NH) g_denom[i] = 0.0f;
}

// ---------------------------------------------------------------------------
// Projections: TP=64 tiles, 256 threads, 2 CTAs/SM. Three passes
// (Wq->g_q, Wk->g_k, Wv->g_v), W re-staged per pass, A per tile.
// ---------------------------------------------------------------------------
__global__ __launch_bounds__(256, 2) void k_proj_mma(
    const float* __restrict__ query, const float* __restrict__ key,
    const float* __restrict__ Wq, const float* __restrict__ Wkv, int n)
{
    extern __shared__ char smem[];
    uint32_t sbase = smem_u32(smem);

    int tid  = threadIdx.x;
    int warp = tid >> 5;
    int lane = tid & 31;
    int wm   = warp >> 2;      // 0..1 (32 rows)
    int wn   = warp & 3;       // 0..3 (32 cols)
    int g    = lane >> 2;
    int t4   = lane & 3;

    uint32_t aoff = (uint32_t)(((lane & 7) + 8 * ((lane >> 3) & 1)) * PITCHB
                               + ((lane >> 4) & 1) * 16);
    uint32_t boff = (uint32_t)(((lane & 7) + 8 * ((lane >> 4) & 1)) * PITCHB
                               + ((lane >> 3) & 1) * 16);
    uint32_t a_base = sbase + PM_A + (uint32_t)(wm * 32) * PITCHB + aoff;
    uint32_t b_base = sbase + PM_W + (uint32_t)(wn * 32) * PITCHB + boff;

    int ntiles = (n + TP - 1) / TP;
    float acc[2][4][4];

#pragma unroll 1
    for (int pass = 0; pass < 3; pass++) {
        const float* Asrc = (pass == 0) ? query : key;
        const float* Wsrc = (pass == 0) ? Wq : Wkv;
        int ldW = (pass == 0) ? HC : COLS;
        int cb  = (pass == 2) ? HC : 0;
        float* outp = (pass == 0) ? g_q : (pass == 1) ? g_k : g_v;

        __syncthreads();  // prior pass readers of W done
        for (int i = tid; i < 128 * 64; i += 256) {
            int nc = i >> 6, kp = i & 63;
            float2 w = make_float2(Wsrc[(2 * kp)     * ldW + cb + nc],
                                   Wsrc[(2 * kp + 1) * ldW + cb + nc]);
            size_t off = (size_t)nc * PITCHB + (size_t)kp * 4;
            split_store(smem + PM_W + off, smem + PM_W + SPLIT_S + off, w);
        }

        for (int tile = blockIdx.x; tile < ntiles; tile += gridDim.x) {
            int nb = tile * TP;
            __syncthreads();
            for (int i = tid; i < TP * 64; i += 256) {
                int r = i >> 6, cp = i & 63;
                int row = nb + r;
                float2 x = (row < n) ? ((const float2*)Asrc)[(size_t)row * 64 + cp]
                                     : make_float2(0.f, 0.f);
                size_t off = (size_t)r * PITCHB + (size_t)cp * 4;
                split_store(smem + PM_A + off, smem + PM_A + PM_AS + off, x);
            }
            __syncthreads();
            mma_warp_tile(acc, a_base, b_base, PM_AS, SPLIT_S);
            store_acc_warp(acc, outp, nb, wm, wn, g, t4, n);
        }
        __syncthreads();  // A readers done before next pass restages W
    }
}

// ---------------------------------------------------------------------------
// Edge kernel — R15-exact, FROZEN (294us): staged GEMM + fused exp/denom.
// ---------------------------------------------------------------------------
__global__ __launch_bounds__(512, 1) void k_edge_mma(
    const float* __restrict__ paired, const float* __restrict__ Wb,
    const int* __restrict__ qidx, const int* __restrict__ kidx,
    float* __restrict__ out_logit, int m)
{
    extern __shared__ char smem[];
    uint32_t sbase = smem_u32(smem);

    int tid  = threadIdx.x;
    int warp = tid >> 5;
    int lane = tid & 31;
    int wm   = warp >> 2;
    int wn   = warp & 3;
    int g    = lane >> 2;
    int t4   = lane & 3;

    int*   s_qi   = (int*)(smem + SM_QI);
    int*   s_ki   = (int*)(smem + SM_KI);
    float* s_part = (float*)(smem + SM_PART);

    for (int i = tid; i < 2 * 128 * 64; i += 512) {
        int kp = i & 63;
        int nc = (i >> 6) & 127;
        int p  = i >> 13;
        int wn_ = nc >> 5, ln = nc & 31;
        int u = ln >> 4, bias = (ln >> 3) & 1, off = ln & 7;
        int ch   = p * 64 + wn_ * 16 + u * 8 + off;
        int wcol = bias * 128 + ch;
        float2 w = make_float2(Wb[(2 * kp)     * COLS + wcol],
                               Wb[(2 * kp + 1) * COLS + wcol]);
        size_t off_b = (size_t)p * SM_WB_P + (size_t)nc * PITCHB + (size_t)kp * 4;
        split_store(smem + SM_WB + off_b, smem + SM_WB + SM_WB_S + off_b, w);
    }

    uint32_t aoff = (uint32_t)(((lane & 7) + 8 * ((lane >> 3) & 1)) * PITCHB
                               + ((lane >> 4) & 1) * 16);
    uint32_t boff = (uint32_t)(((lane & 7) + 8 * ((lane >> 4) & 1)) * PITCHB
                               + ((lane >> 3) & 1) * 16);
    uint32_t a_base = sbase + SM_A  + (uint32_t)(wm * 32) * PITCHB + aoff;
    uint32_t b_base = sbase + SM_WB + (uint32_t)(wn * 32) * PITCHB + boff;

    int ntiles = (m + TE - 1) / TE;
    for (int tile = blockIdx.x; tile < ntiles; tile += gridDim.x) {
        int ebase = tile * TE;
        __syncthreads();

        for (int i = tid; i < TE * 64; i += 512) {
            int r = i >> 6, cp = i & 63;
            int e = ebase + r;
            float2 x = (e < m) ? ((const float2*)paired)[(size_t)e * 64 + cp]
                               : make_float2(0.f, 0.f);
            size_t off_a = (size_t)r * PITCHB + (size_t)cp * 4;
            split_store(smem + SM_A + off_a, smem + SM_A + SM_A_S + off_a, x);
        }
        if (tid < TE) {
            int e = ebase + tid;
            s_qi[tid] = (e < m) ? qidx[e] : 0;
            s_ki[tid] = (e < m) ? kidx[e] : 0;
        }
        __syncthreads();

        float part[4][2];
#pragma unroll
        for (int a = 0; a < 4; a++) { part[a][0] = 0.f; part[a][1] = 0.f; }

#pragma unroll
        for (int p = 0; p < 2; p++) {
            float acc[2][4][4];
#pragma unroll
            for (int mt = 0; mt < 2; mt++)
#pragma unroll
                for (int nt = 0; nt < 4; nt++)
#pragma unroll
                    for (int el = 0; el < 4; el++) acc[mt][nt][el] = 0.f;

#pragma unroll 2
            for (int ks = 0; ks < 8; ks++) {
                uint32_t bh[4][2], bl[4][2], ah[2][4], al[2][4];
                uint32_t bk = b_base + (uint32_t)p * SM_WB_P + (uint32_t)ks * 32;
#pragma unroll
                for (int u2 = 0; u2 < 2; u2++) {
                    uint32_t tmp[4];
                    LDSM_X4(tmp, bk + (uint32_t)(u2 * 16) * PITCHB);
                    bh[2*u2][0] = tmp[0]; bh[2*u2][1] = tmp[1];
                    bh[2*u2+1][0] = tmp[2]; bh[2*u2+1][1] = tmp[3];
                    LDSM_X4(tmp, bk + SM_WB_S + (uint32_t)(u2 * 16) * PITCHB);
                    bl[2*u2][0] = tmp[0]; bl[2*u2][1] = tmp[1];
                    bl[2*u2+1][0] = tmp[2]; bl[2*u2+1][1] = tmp[3];
                }
                uint32_t ak_ = a_base + (uint32_t)ks * 32;
#pragma unroll
                for (int mt = 0; mt < 2; mt++) {
                    LDSM_X4(ah[mt], ak_ + (uint32_t)(mt * 16) * PITCHB);
                    LDSM_X4(al[mt], ak_ + SM_A_S + (uint32_t)(mt * 16) * PITCHB);
                }
#pragma unroll
                for (int mt = 0; mt < 2; mt++)
#pragma unroll
                    for (int nt = 0; nt < 4; nt++) {
                        MMA_BF16(acc[mt][nt], ah[mt], bh[nt]);
                        MMA_BF16(acc[mt][nt], ah[mt], bl[nt]);
                        MMA_BF16(acc[mt][nt], al[mt], bh[nt]);
                    }
            }

#pragma unroll
            for (int mt = 0; mt < 2; mt++)
#pragma unroll
                for (int rh = 0; rh < 2; rh++) {
                    int eli = wm * 32 + mt * 16 + g + rh * 8;
                    const float* qrow = g_q + (size_t)s_qi[eli] * HC;
                    const float* krow = g_k + (size_t)s_ki[eli] * HC;
#pragma unroll
                    for (int u = 0; u < 2; u++) {
                        int c = p * 64 + wn * 16 + u * 8 + t4 * 2;
                        float2 q2 = *(const float2*)(qrow + c);
                        float2 k2 = *(const float2*)(krow + c);
                        float bm0 = acc[mt][2*u][rh*2],   bm1 = acc[mt][2*u][rh*2+1];
                        float ba0 = acc[mt][2*u+1][rh*2], ba1 = acc[mt][2*u+1][rh*2+1];
                        float qk0 = q2.x * k2.x;
                        float qk1 = q2.y * k2.y;
                        part[mt*2+rh][0] += fmaf(qk0, bm0, qk0) + q2.x * ba0;
                        part[mt*2+rh][1] += fmaf(qk1, bm1, qk1) + q2.y * ba1;
                    }
                }
        }

#pragma unroll
        for (int mt = 0; mt < 2; mt++)
#pragma unroll
            for (int rh = 0; rh < 2; rh++) {
                int eli = wm * 32 + mt * 16 + g + rh * 8;
                float2* sp = (float2*)&s_part[wn * 1024 + eli * 8 + t4 * 2];
                *sp = make_float2(part[mt*2+rh][0], part[mt*2+rh][1]);
            }
        __syncthreads();

        // combine 4 N-groups; emit logit, exp, denom accumulation
#pragma unroll
        for (int j = 0; j < 2; j++) {
            int i  = tid + j * 512;
            int el = i >> 3, h = i & 7;
            int e  = ebase + el;
            if (e < m) {
                float lg = (s_part[i] + s_part[1024 + i])
                         + (s_part[2048 + i] + s_part[3072 + i]);
                out_logit[e * NH + h] = lg;
                float ex = expf(lg);
                g_ex[e * NH + h] = ex;
                atomicAdd(&g_denom[s_qi[el] * NH + h], ex);
            }
        }
    }
}

// ---------------------------------------------------------------------------
// scatter (normalized): agg[qi] += (ex/denom) * v[ki]
// ---------------------------------------------------------------------------
__global__ void k_scatter(const int* __restrict__ qidx,
                          const int* __restrict__ kidx, int m)
{
    int i = blockIdx.x * blockDim.x + threadIdx.x;
    if (i >= m * 32) return;
    int e  = i >> 5;
    int c4 = (i & 31) << 2;
    int qi = qidx[e];
    float4 v  = *(const float4*)&g_v[kidx[e] * HC + c4];
    float4 ex = *(const float4*)&g_ex[(e << 3) + (c4 & 7)];
    float4 dn = *(const float4*)&g_denom[qi * NH + (c4 & 7)];
    float4 val = make_float4((ex.x / dn.x) * v.x, (ex.y / dn.y) * v.y,
                             (ex.z / dn.z) * v.z, (ex.w / dn.w) * v.w);
    atomicAdd((float4*)&g_agg[qi * HC + c4], val);
}

// ---------------------------------------------------------------------------
// result = agg @ Wo: TP=64 tiles, 256 threads, 2 CTAs/SM.
// ---------------------------------------------------------------------------
__global__ __launch_bounds__(256, 2) void k_out_mma(
    const float* __restrict__ Wo, float* __restrict__ out, int n)
{
    extern __shared__ char smem[];
    uint32_t sbase = smem_u32(smem);

    int tid  = threadIdx.x;
    int warp = tid >> 5;
    int lane = tid & 31;
    int wm   = warp >> 2;
    int wn   = warp & 3;
    int g    = lane >> 2;
    int t4   = lane & 3;

    uint32_t aoff = (uint32_t)(((lane & 7) + 8 * ((lane >> 3) & 1)) * PITCHB
                               + ((lane >> 4) & 1) * 16);
    uint32_t boff = (uint32_t)(((lane & 7) + 8 * ((lane >> 4) & 1)) * PITCHB
                               + ((lane >> 3) & 1) * 16);
    uint32_t a_base = sbase + PM_A + (uint32_t)(wm * 32) * PITCHB + aoff;
    uint32_t b_base = sbase + PM_W + (uint32_t)(wn * 32) * PITCHB + boff;

    for (int i = tid; i < 128 * 64; i += 256) {
        int nc = i >> 6, kp = i & 63;
        float2 w = make_float2(Wo[(2 * kp)     * HC + nc],
                               Wo[(2 * kp + 1) * HC + nc]);
        size_t off = (size_t)nc * PITCHB + (size_t)kp * 4;
        split_store(smem + PM_W + off, smem + PM_W + SPLIT_S + off, w);
    }

    int ntiles = (n + TP - 1) / TP;
    float acc[2][4][4];
    for (int tile = blockIdx.x; tile < ntiles; tile += gridDim.x) {
        int nb = tile * TP;
        __syncthreads();
        for (int i = tid; i < TP * 64; i += 256) {
            int r = i >> 6, cp = i & 63;
            int row = nb + r;
            float2 x = (row < n) ? ((const float2*)g_agg)[(size_t)row * 64 + cp]
                                 : make_float2(0.f, 0.f);
            size_t off = (size_t)r * PITCHB + (size_t)cp * 4;
            split_store(smem + PM_A + off, smem + PM_A + PM_AS + off, x);
        }
        __syncthreads();
        mma_warp_tile(acc, a_base, b_base, PM_AS, SPLIT_S);
        store_acc_warp(acc, out, nb, wm, wn, g, t4, n);
    }
}

// ---------------------------------------------------------------------------
extern "C" void kernel_launch(void* const* d_in, const int* in_sizes, int n_in,
                              void* d_out, int out_size)
{
    const float* query  = (const float*)d_in[0];
    const float* key    = (const float*)d_in[1];
    const int*   qidx   = (const int*)  d_in[2];
    const int*   kidx   = (const int*)  d_in[3];
    const float* paired = (const float*)d_in[4];
    const float* Wq     = (const float*)d_in[5];
    const float* Wkv    = (const float*)d_in[6];
    const float* Wb     = (const float*)d_in[7];
    const float* Wo     = (const float*)d_in[8];

    int n = in_sizes[0] / HC;   // 50000
    int m = in_sizes[2];        // 400000

    float* out_result = (float*)d_out;           // n*HC
    float* out_logit  = (float*)d_out + n * HC;  // m*NH

    cudaFuncSetAttribute(k_edge_mma, cudaFuncAttributeMaxDynamicSharedMemorySize,
                         SM_EDGE_TOTAL);
    cudaFuncSetAttribute(k_proj_mma, cudaFuncAttributeMaxDynamicSharedMemorySize,
                         PM_TOTAL);
    cudaFuncSetAttribute(k_out_mma, cudaFuncAttributeMaxDynamicSharedMemorySize,
                         PM_TOTAL);

    int dev = 0, nsm = 148;
    cudaGetDevice(&dev);
    cudaDeviceGetAttribute(&nsm, cudaDevAttrMultiProcessorCount, dev);

    int etiles = (m + TE - 1) / TE;
    int egrid  = etiles < nsm ? etiles : nsm;
    int ptiles = (n + TP - 1) / TP;
    int pgrid  = ptiles < 2 * nsm ? ptiles : 2 * nsm;

    int half = (n * HC) / 2;

    // k_proj_mma in the profiled (4th) slot to verify the occupancy theory.
    k_init_agg<<<(half + 255) / 256, 256>>>(0, half);                    // 1
    k_init_agg<<<(n * HC - half + 255) / 256, 256>>>(half, n * HC);      // 2
    k_init_denom<<<(n * NH + 255) / 256, 256>>>(n);                      // 3
    k_proj_mma<<<pgrid, 256, PM_TOTAL>>>(query, key, Wq, Wkv, n);        // 4
    k_edge_mma<<<egrid, 512, SM_EDGE_TOTAL>>>(paired, Wb, qidx, kidx,    // 5
                                              out_logit, m);
    k_scatter<<<(m * 32 + 255) / 256, 256>>>(qidx, kidx, m);             // 6
    k_out_mma<<<pgrid, 256, PM_TOTAL>>>(Wo, out_result, n);              // 7
}